// round 2
// baseline (speedup 1.0000x reference)
#include <cuda_runtime.h>

#define Hh 256
#define Tt 187
#define Bb 1024
#define Cc 5
#define MB 8
#define NCTA (Bb / MB)   // 128 CTAs

// Packed weight scratch: layout [k/4][j][4] so thread j loads a float4 of
// 4 consecutive k's for its column j, coalesced across lanes (16B/lane).
__device__ float g_Wp0[Hh * Hh];      // packed W_hh0
__device__ float g_Wpih1[Hh * Hh];    // packed W_ih1
__device__ float g_Wp1[Hh * Hh];      // packed W_hh1

__global__ void pack_kernel(const float* __restrict__ W_hh0,
                            const float* __restrict__ W_ih1,
                            const float* __restrict__ W_hh1) {
    int j = blockIdx.x;      // output column (row of W)
    int k = threadIdx.x;     // input index
    int src = j * Hh + k;                       // coalesced read across k
    int dst = ((k >> 2) * Hh + j) * 4 + (k & 3);
    g_Wp0[dst]   = W_hh0[src];
    g_Wpih1[dst] = W_ih1[src];
    g_Wp1[dst]   = W_hh1[src];
}

union F2U { unsigned long long u; float2 f; };

__device__ __forceinline__ unsigned long long f32x2_fma(
    unsigned long long a, unsigned long long b, unsigned long long c) {
    unsigned long long d;
    asm("fma.rn.f32x2 %0, %1, %2, %3;" : "=l"(d) : "l"(a), "l"(b), "l"(c));
    return d;
}

__global__ void __launch_bounds__(256, 1) rnn_fused_kernel(
    const float* __restrict__ x,
    const float* __restrict__ W_ih0,
    const float* __restrict__ b_ih0, const float* __restrict__ b_hh0,
    const float* __restrict__ b_ih1, const float* __restrict__ b_hh1,
    const float* __restrict__ W_fc,  const float* __restrict__ b_fc,
    float* __restrict__ out)
{
    __shared__ __align__(16) float h0s[MB * Hh];
    __shared__ __align__(16) float h1s[MB * Hh];
    __shared__ float xs[MB * Tt];

    const int j  = threadIdx.x;        // this thread owns hidden column j
    const int b0 = blockIdx.x * MB;    // first batch row of this CTA

    // x rows b0..b0+7 are contiguous in memory: coalesced bulk copy.
    for (int i = j; i < MB * Tt; i += 256) xs[i] = x[b0 * Tt + i];
    for (int i = j; i < MB * Hh; i += 256) { h0s[i] = 0.f; h1s[i] = 0.f; }

    const float wih0  = W_ih0[j];
    const float bias0 = b_ih0[j] + b_hh0[j];
    const float bias1 = b_ih1[j] + b_hh1[j];

    __syncthreads();

    for (int t = 0; t < Tt; ++t) {
        // ---------------- layer 0: h0 = tanh(x*Wih0 + bias + h0 @ Whh0^T) ----
        unsigned long long acc[MB];
        #pragma unroll
        for (int b = 0; b < MB; ++b) acc[b] = 0ULL;

        #pragma unroll 8
        for (int k4 = 0; k4 < Hh / 4; ++k4) {
            const ulonglong2 w =
                *reinterpret_cast<const ulonglong2*>(&g_Wp0[(k4 * Hh + j) * 4]);
            #pragma unroll
            for (int b = 0; b < MB; ++b) {
                ulonglong2 h =
                    *reinterpret_cast<const ulonglong2*>(&h0s[b * Hh + k4 * 4]);
                acc[b] = f32x2_fma(h.x, w.x, acc[b]);
                acc[b] = f32x2_fma(h.y, w.y, acc[b]);
            }
        }

        float hn[MB];
        #pragma unroll
        for (int b = 0; b < MB; ++b) {
            F2U u; u.u = acc[b];
            float pre = xs[b * Tt + t] * wih0 + bias0 + (u.f.x + u.f.y);
            hn[b] = tanhf(pre);
        }
        __syncthreads();                  // everyone done reading old h0s
        #pragma unroll
        for (int b = 0; b < MB; ++b) h0s[b * Hh + j] = hn[b];
        __syncthreads();                  // new h0s visible

        // ------- layer 1: h1 = tanh(h0 @ Wih1^T + bias + h1 @ Whh1^T) --------
        #pragma unroll
        for (int b = 0; b < MB; ++b) acc[b] = 0ULL;

        #pragma unroll 4
        for (int k4 = 0; k4 < Hh / 4; ++k4) {
            const ulonglong2 wa =
                *reinterpret_cast<const ulonglong2*>(&g_Wpih1[(k4 * Hh + j) * 4]);
            const ulonglong2 wb =
                *reinterpret_cast<const ulonglong2*>(&g_Wp1[(k4 * Hh + j) * 4]);
            #pragma unroll
            for (int b = 0; b < MB; ++b) {
                ulonglong2 ha =
                    *reinterpret_cast<const ulonglong2*>(&h0s[b * Hh + k4 * 4]);
                ulonglong2 hb =
                    *reinterpret_cast<const ulonglong2*>(&h1s[b * Hh + k4 * 4]);
                acc[b] = f32x2_fma(ha.x, wa.x, acc[b]);
                acc[b] = f32x2_fma(ha.y, wa.y, acc[b]);
                acc[b] = f32x2_fma(hb.x, wb.x, acc[b]);
                acc[b] = f32x2_fma(hb.y, wb.y, acc[b]);
            }
        }
        #pragma unroll
        for (int b = 0; b < MB; ++b) {
            F2U u; u.u = acc[b];
            hn[b] = tanhf(bias1 + (u.f.x + u.f.y));
        }
        __syncthreads();
        #pragma unroll
        for (int b = 0; b < MB; ++b) h1s[b * Hh + j] = hn[b];
        __syncthreads();
    }

    // ---------------- final FC: out[b] = h1_last @ W_fc^T + b_fc -------------
    if (j < Cc * MB) {
        int c = j / MB, b = j % MB;
        float s = b_fc[c];
        #pragma unroll 8
        for (int h = 0; h < Hh; ++h) s += h1s[b * Hh + h] * W_fc[c * Hh + h];
        out[(b0 + b) * Cc + c] = s;
    }
}

extern "C" void kernel_launch(void* const* d_in, const int* in_sizes, int n_in,
                              void* d_out, int out_size) {
    const float* x     = (const float*)d_in[0];
    const float* W_ih0 = (const float*)d_in[1];
    const float* W_hh0 = (const float*)d_in[2];
    const float* b_ih0 = (const float*)d_in[3];
    const float* b_hh0 = (const float*)d_in[4];
    const float* W_ih1 = (const float*)d_in[5];
    const float* W_hh1 = (const float*)d_in[6];
    const float* b_ih1 = (const float*)d_in[7];
    const float* b_hh1 = (const float*)d_in[8];
    const float* W_fc  = (const float*)d_in[9];
    const float* b_fc  = (const float*)d_in[10];
    float* out = (float*)d_out;

    pack_kernel<<<Hh, Hh>>>(W_hh0, W_ih1, W_hh1);
    rnn_fused_kernel<<<NCTA, 256>>>(x, W_ih0, b_ih0, b_hh0,
                                    b_ih1, b_hh1, W_fc, b_fc, out);
}